// round 14
// baseline (speedup 1.0000x reference)
#include <cuda_runtime.h>
#include <cuda_fp16.h>
#include <cstdint>

#define SEQ   4096
#define EMB   1024
#define NH    16
#define HD    64
#define WIN   256
#define QKV_N 3072

// ---- fp16 GEMM tiling: 128x256x64, 8 warps (2x4), warp tile 64x64 ----
#define BM 128
#define BN 256
#define BK 64
#define STG 3
#define LHW 72                               // halves per smem row (64 + 8 pad)
#define TILE_A_H (128 * LHW)
#define TILE_B_H (256 * LHW)
#define STAGE_H (TILE_A_H + TILE_B_H)
#define GEMM_SMEM (STG * STAGE_H * 2)        // 165888 B

// ---- attention (fp16): strides in halves ----
#define LH 72
#define QS_OFF  0
#define PS_OFF  (64 * LH)
#define KS_OFF  (2 * 64 * LH)
#define VS_OFF  (4 * 64 * LH)
#define ATTN_SMEM ((6 * 64 * LH) * 2)

static __device__ __half g_ah[SEQ * EMB];      // x fp16 [seq][emb]
static __device__ __half g_wqt[QKV_N * EMB];   // w_qkv^T fp16 [N][K]
static __device__ __half g_wot[EMB * EMB];     // w_out^T fp16 [N][K]
static __device__ __half g_qh[SEQ * EMB];      // Q fp16
static __device__ __half g_kh[SEQ * EMB];      // K fp16
static __device__ __half g_vt[EMB * SEQ];      // V fp16 transposed [(h*64+d)][seq]
static __device__ __half g_ch[SEQ * EMB];      // ctx fp16

__device__ __forceinline__ uint32_t smem_u32(const void* p) {
    uint32_t a;
    asm("{ .reg .u64 t; cvta.to.shared.u64 t, %1; cvt.u32.u64 %0, t; }" : "=r"(a) : "l"(p));
    return a;
}
__device__ __forceinline__ void mma_f16(float d[4], const uint32_t a[4], const uint32_t b[2]) {
    asm volatile(
        "mma.sync.aligned.m16n8k16.row.col.f32.f16.f16.f32 "
        "{%0,%1,%2,%3}, {%4,%5,%6,%7}, {%8,%9}, {%0,%1,%2,%3};\n"
        : "+f"(d[0]), "+f"(d[1]), "+f"(d[2]), "+f"(d[3])
        : "r"(a[0]), "r"(a[1]), "r"(a[2]), "r"(a[3]), "r"(b[0]), "r"(b[1]));
}
__device__ __forceinline__ void ldsm4(uint32_t r[4], uint32_t addr) {
    asm volatile("ldmatrix.sync.aligned.m8n8.x4.shared.b16 {%0,%1,%2,%3}, [%4];"
                 : "=r"(r[0]), "=r"(r[1]), "=r"(r[2]), "=r"(r[3]) : "r"(addr));
}
__device__ __forceinline__ void cp16(const void* smem_dst, const void* gsrc) {
    uint32_t saddr = smem_u32(smem_dst);
    asm volatile("cp.async.cg.shared.global [%0], [%1], 16;\n" :: "r"(saddr), "l"(gsrc) : "memory");
}

// ---------------------------------------------------------------------------
__global__ __launch_bounds__(256) void to_half(const float4* __restrict__ src,
                                               __half2* __restrict__ dst, int n4) {
    int i = blockIdx.x * blockDim.x + threadIdx.x;
    if (i < n4) {
        float4 v = src[i];
        dst[2 * i]     = __floats2half2_rn(v.x, v.y);
        dst[2 * i + 1] = __floats2half2_rn(v.z, v.w);
    }
}

__global__ __launch_bounds__(256) void transpose_half(const float* __restrict__ W,
                                                      __half* __restrict__ T,
                                                      int K, int N) {
    __shared__ float tile[32][33];
    const int tx = threadIdx.x & 31, ty = threadIdx.x >> 5;
    const int n0 = blockIdx.x * 32, k0 = blockIdx.y * 32;
#pragma unroll
    for (int i = 0; i < 4; i++)
        tile[ty + 8 * i][tx] = W[(size_t)(k0 + ty + 8 * i) * N + n0 + tx];
    __syncthreads();
#pragma unroll
    for (int i = 0; i < 4; i++)
        T[(size_t)(n0 + ty + 8 * i) * K + k0 + tx] = __float2half_rn(tile[tx][ty + 8 * i]);
}

// ---------------------------------------------------------------------------
// fp16 tensor-core GEMM, 128x256 CTA tile, warp tile 64x64, ldmatrix loads.
// MODE 0: fp32 C store. MODE 1: qkv split epilogue (bx 0-3 Q, 4-7 K, 8-11 V^T).
// ---------------------------------------------------------------------------
template <int MODE>
__global__ __launch_bounds__(256, 1) void hgemm(const __half* __restrict__ A,
                                                const __half* __restrict__ Bt,
                                                float* __restrict__ C,
                                                __half* __restrict__ qh,
                                                __half* __restrict__ kh,
                                                __half* __restrict__ vt,
                                                int M, int N, int K) {
    extern __shared__ __half smh[];
    const uint32_t sb = smem_u32(smh);

    const int t    = threadIdx.x;
    const int w    = t >> 5;
    const int lane = t & 31;
    const int wm   = w >> 2;        // 0..1
    const int wn   = w & 3;         // 0..3 -> 64-wide n slice
    const int lr   = lane >> 2;
    const int lc   = lane & 3;
    const int bx   = blockIdx.x;
    const int by   = blockIdx.y;

    const int l15  = lane & 15;
    const int lhi8 = (lane >> 4) * 8;
    const int brow = ((lane >> 4) << 3) + (lane & 7);
    const int bk8  = ((lane >> 3) & 1) * 8;

    float acc[4][8][4];
#pragma unroll
    for (int i = 0; i < 4; i++)
#pragma unroll
        for (int j = 0; j < 8; j++)
#pragma unroll
            for (int c = 0; c < 4; c++) acc[i][j][c] = 0.0f;

    const int NT = K / BK;
    const int ldr = t >> 3;              // 0..31
    const int ldc = (t & 7) * 8;

#define LOAD_TILE(stage, ktile)                                                         \
    {                                                                                   \
        __half* Ad = smh + (stage) * STAGE_H;                                           \
        __half* Bd = Ad + TILE_A_H;                                                     \
        const int k0 = (ktile) * BK;                                                    \
        _Pragma("unroll")                                                               \
        for (int i = 0; i < 4; i++) {                                                   \
            int r = ldr + 32 * i;                                                       \
            cp16(&Ad[r * LHW + ldc], &A[(size_t)(by * BM + r) * K + k0 + ldc]);         \
        }                                                                               \
        _Pragma("unroll")                                                               \
        for (int i = 0; i < 8; i++) {                                                   \
            int r = ldr + 32 * i;                                                       \
            cp16(&Bd[r * LHW + ldc], &Bt[(size_t)(bx * BN + r) * K + k0 + ldc]);        \
        }                                                                               \
        asm volatile("cp.async.commit_group;\n" ::: "memory");                          \
    }

    LOAD_TILE(0, 0);
    LOAD_TILE(1, 1);

    for (int kt = 0; kt < NT; kt++) {
        if (kt + 2 < NT) asm volatile("cp.async.wait_group 1;\n" ::: "memory");
        else             asm volatile("cp.async.wait_group 0;\n" ::: "memory");
        __syncthreads();

        if (kt + 2 < NT) LOAD_TILE((kt + 2) % STG, kt + 2);

        const uint32_t Ab = sb + (uint32_t)((kt % STG) * STAGE_H) * 2;
        const uint32_t Bb = Ab + TILE_A_H * 2;

#pragma unroll
        for (int ks = 0; ks < 4; ks++) {
            uint32_t af[4][4], bq[4][4];
#pragma unroll
            for (int mi = 0; mi < 4; mi++)
                ldsm4(af[mi], Ab + (uint32_t)(((wm * 64 + mi * 16 + l15) * LHW) + ks * 16 + lhi8) * 2);
#pragma unroll
            for (int pr = 0; pr < 4; pr++)
                ldsm4(bq[pr], Bb + (uint32_t)(((wn * 64 + pr * 16 + brow) * LHW) + ks * 16 + bk8) * 2);
#pragma unroll
            for (int mi = 0; mi < 4; mi++)
#pragma unroll
                for (int ni = 0; ni < 8; ni++)
                    mma_f16(acc[mi][ni], af[mi], &bq[ni >> 1][(ni & 1) * 2]);
        }
    }

    if (MODE == 1 && bx >= (2 * EMB) / BN) {
        // ---- V tiles: transpose through smem, coalesced V^T stores ----
        __syncthreads();
        __half* Vt = smh;                      // [256 dims][136 seq-halves]
#pragma unroll
        for (int mi = 0; mi < 4; mi++) {
            const int sl = wm * 64 + mi * 16 + lr;
#pragma unroll
            for (int ni = 0; ni < 8; ni++) {
                const int d0 = wn * 64 + ni * 8 + 2 * lc;
                Vt[d0 * 136 + sl]           = __float2half_rn(acc[mi][ni][0]);
                Vt[(d0 + 1) * 136 + sl]     = __float2half_rn(acc[mi][ni][1]);
                Vt[d0 * 136 + sl + 8]       = __float2half_rn(acc[mi][ni][2]);
                Vt[(d0 + 1) * 136 + sl + 8] = __float2half_rn(acc[mi][ni][3]);
            }
        }
        __syncthreads();
        const int vcol0 = bx * BN - 2 * EMB;   // dim offset within [0,1024)
#pragma unroll
        for (int i = 0; i < 16; i++) {
            int id = t + 256 * i;              // 0..4095
            int row = id >> 4, ch = id & 15;
            *(uint4*)&vt[(size_t)(vcol0 + row) * SEQ + by * BM + ch * 8] =
                *(const uint4*)&Vt[row * 136 + ch * 8];
        }
        return;
    }

#pragma unroll
    for (int mi = 0; mi < 4; mi++) {
        const int r0 = by * BM + wm * 64 + mi * 16 + lr;
#pragma unroll
        for (int ni = 0; ni < 8; ni++) {
            const int c0 = bx * BN + wn * 64 + ni * 8 + 2 * lc;
            float v0 = acc[mi][ni][0], v1 = acc[mi][ni][1];
            float v2 = acc[mi][ni][2], v3 = acc[mi][ni][3];
            if (MODE == 0) {
                *(float2*)&C[(size_t)r0 * N + c0]       = make_float2(v0, v1);
                *(float2*)&C[(size_t)(r0 + 8) * N + c0] = make_float2(v2, v3);
            } else {
                if (c0 < EMB) {
                    *(__half2*)&qh[(size_t)r0 * EMB + c0]       = __floats2half2_rn(v0, v1);
                    *(__half2*)&qh[(size_t)(r0 + 8) * EMB + c0] = __floats2half2_rn(v2, v3);
                } else {
                    const int cc = c0 - EMB;
                    *(__half2*)&kh[(size_t)r0 * EMB + cc]       = __floats2half2_rn(v0, v1);
                    *(__half2*)&kh[(size_t)(r0 + 8) * EMB + cc] = __floats2half2_rn(v2, v3);
                }
            }
        }
    }
#undef LOAD_TILE
}

// ---------------------------------------------------------------------------
// fp16 attention with ldmatrix fragment loads + per-tile mask specialization.
// (round-12 proven, unchanged)
// ---------------------------------------------------------------------------
__global__ __launch_bounds__(128) void attn_h(const __half* __restrict__ qh,
                                              const __half* __restrict__ kh,
                                              const __half* __restrict__ vt,
                                              __half* __restrict__ ctx) {
    extern __shared__ __half sh[];
    __half* Qs = sh + QS_OFF;
    __half* Ps = sh + PS_OFF;
    const uint32_t sb = smem_u32(sh);

    const int qb = blockIdx.x;
    const int h  = blockIdx.y;
    const int t  = threadIdx.x;
    const int w  = t >> 5;
    const int lane = t & 31;
    const int lr = lane >> 2;
    const int lc = lane & 3;
    const int q0 = qb * 64;
    const int col0 = h * HD;

    const int l15  = lane & 15;
    const int lhi8 = (lane >> 4) * 8;
    const int brow = ((lane >> 4) << 3) + (lane & 7);
    const int bk8  = ((lane >> 3) & 1) * 8;

#define LOADKV(s, kt)                                                                   \
    {                                                                                   \
        __half* Kd = sh + KS_OFF + (s) * 64 * LH;                                       \
        __half* Vd = sh + VS_OFF + (s) * 64 * LH;                                       \
        const int kk0 = (kt) * 64;                                                      \
        _Pragma("unroll")                                                               \
        for (int i = 0; i < 4; i++) {                                                   \
            int id = t + 128 * i;                                                       \
            int r = id >> 3, c = (id & 7) << 3;                                         \
            cp16(&Kd[r * LH + c], &kh[(size_t)(kk0 + r) * EMB + col0 + c]);             \
            cp16(&Vd[r * LH + c], &vt[(size_t)(col0 + r) * SEQ + kk0 + c]);             \
        }                                                                               \
        asm volatile("cp.async.commit_group;\n" ::: "memory");                          \
    }

#pragma unroll
    for (int i = 0; i < 4; i++) {
        int id = t + 128 * i;
        int r = id >> 3, c = (id & 7) << 3;
        cp16(&Qs[r * LH + c], &qh[(size_t)(q0 + r) * EMB + col0 + c]);
    }

    float o[8][4];
#pragma unroll
    for (int nt = 0; nt < 8; nt++)
#pragma unroll
        for (int c = 0; c < 4; c++) o[nt][c] = 0.0f;
    float m[2] = {-1e30f, -1e30f};
    float l[2] = {0.0f, 0.0f};

    const int ktlo = (qb >= 4) ? qb - 4 : 0;
    LOADKV(0, ktlo);

    const uint32_t qfb = sb + (uint32_t)(((16 * w + l15) * LH) + lhi8) * 2;
    const uint32_t pfb = qfb + (uint32_t)(PS_OFF) * 2;

    for (int kt = ktlo; kt <= qb; kt++) {
        const int s = (kt - ktlo) & 1;
        const int k0 = kt * 64;
        const int mode = (kt == qb) ? 1 : ((qb >= 4 && kt == qb - 4) ? 2 : 0);

        asm volatile("cp.async.wait_group 0;\n" ::: "memory");
        __syncthreads();

        if (kt < qb) LOADKV(s ^ 1, kt + 1);

        const uint32_t Kb = sb + (uint32_t)((KS_OFF + s * 64 * LH) + (brow * LH) + bk8) * 2;
        const uint32_t Vb = sb + (uint32_t)((VS_OFF + s * 64 * LH) + (brow * LH) + bk8) * 2;

        float acc[8][4];
#pragma unroll
        for (int nt = 0; nt < 8; nt++)
#pragma unroll
            for (int c = 0; c < 4; c++) acc[nt][c] = 0.0f;

#pragma unroll
        for (int ks = 0; ks < 4; ks++) {
            uint32_t af[4];
            ldsm4(af, qfb + ks * 32);
#pragma unroll
            for (int pr = 0; pr < 4; pr++) {
                uint32_t bq[4];
                ldsm4(bq, Kb + (uint32_t)(pr * 16 * LH) * 2 + ks * 32);
                mma_f16(acc[2 * pr], af, &bq[0]);
                mma_f16(acc[2 * pr + 1], af, &bq[2]);
            }
        }

#pragma unroll
        for (int i = 0; i < 2; i++) {
            const int qi = q0 + 16 * w + lr + 8 * i;
            float sv[16];
            float mt = -1e30f;
#pragma unroll
            for (int nt = 0; nt < 8; nt++) {
#pragma unroll
                for (int c = 0; c < 2; c++) {
                    int kj = k0 + 8 * nt + 2 * lc + c;
                    bool ok = (mode == 0) ||
                              (mode == 1 ? (kj <= qi) : (kj > qi - WIN));
                    float sx = acc[nt][2 * i + c] * 0.125f;
                    sv[nt * 2 + c] = ok ? sx : -1e30f;
                    mt = fmaxf(mt, sv[nt * 2 + c]);
                }
            }
            mt = fmaxf(mt, __shfl_xor_sync(0xffffffffu, mt, 1));
            mt = fmaxf(mt, __shfl_xor_sync(0xffffffffu, mt, 2));

            float alpha = 1.0f;
            if (mt > m[i]) { alpha = __expf(m[i] - mt); m[i] = mt; }

            float ls = 0.0f;
            float p[16];
#pragma unroll
            for (int j = 0; j < 16; j++) {
                p[j] = (sv[j] > -1e29f) ? __expf(sv[j] - m[i]) : 0.0f;
                ls += p[j];
            }
            ls += __shfl_xor_sync(0xffffffffu, ls, 1);
            ls += __shfl_xor_sync(0xffffffffu, ls, 2);

            l[i] = l[i] * alpha + ls;
#pragma unroll
            for (int nt = 0; nt < 8; nt++) {
                o[nt][2 * i]     *= alpha;
                o[nt][2 * i + 1] *= alpha;
                *(__half2*)&Ps[(16 * w + lr + 8 * i) * LH + 8 * nt + 2 * lc] =
                    __floats2half2_rn(p[nt * 2], p[nt * 2 + 1]);
            }
        }
        __syncwarp();

#pragma unroll
        for (int ks = 0; ks < 4; ks++) {
            uint32_t pa[4];
            ldsm4(pa, pfb + ks * 32);
#pragma unroll
            for (int pr = 0; pr < 4; pr++) {
                uint32_t vq[4];
                ldsm4(vq, Vb + (uint32_t)(pr * 16 * LH) * 2 + ks * 32);
                mma_f16(o[2 * pr], pa, &vq[0]);
                mma_f16(o[2 * pr + 1], pa, &vq[2]);
            }
        }
        __syncwarp();
    }

    const float inv0 = 1.0f / l[0];
    const float inv1 = 1.0f / l[1];
    const int row0 = q0 + 16 * w + lr;
#pragma unroll
    for (int nt = 0; nt < 8; nt++) {
        int c0 = col0 + 8 * nt + 2 * lc;
        *(__half2*)&ctx[(size_t)row0 * EMB + c0] =
            __floats2half2_rn(o[nt][0] * inv0, o[nt][1] * inv0);
        *(__half2*)&ctx[(size_t)(row0 + 8) * EMB + c0] =
            __floats2half2_rn(o[nt][2] * inv1, o[nt][3] * inv1);
    }
#undef LOADKV
}

// ---------------------------------------------------------------------------
extern "C" void kernel_launch(void* const* d_in, const int* in_sizes, int n_in,
                              void* d_out, int out_size) {
    const float* x     = (const float*)d_in[0];
    const float* w_qkv = (const float*)d_in[2];
    const float* w_out = (const float*)d_in[3];
    float* out = (float*)d_out;

    __half *ah, *wqt, *wot, *qhp, *khp, *vtp, *chp;
    cudaGetSymbolAddress((void**)&ah, g_ah);
    cudaGetSymbolAddress((void**)&wqt, g_wqt);
    cudaGetSymbolAddress((void**)&wot, g_wot);
    cudaGetSymbolAddress((void**)&qhp, g_qh);
    cudaGetSymbolAddress((void**)&khp, g_kh);
    cudaGetSymbolAddress((void**)&vtp, g_vt);
    cudaGetSymbolAddress((void**)&chp, g_ch);

    cudaFuncSetAttribute(attn_h, cudaFuncAttributeMaxDynamicSharedMemorySize, ATTN_SMEM);
    cudaFuncSetAttribute(hgemm<0>, cudaFuncAttributeMaxDynamicSharedMemorySize, GEMM_SMEM);
    cudaFuncSetAttribute(hgemm<1>, cudaFuncAttributeMaxDynamicSharedMemorySize, GEMM_SMEM);

    // 0) prep
    to_half<<<(SEQ * EMB / 4 + 255) / 256, 256>>>((const float4*)x, (__half2*)ah, SEQ * EMB / 4);
    transpose_half<<<dim3(QKV_N / 32, EMB / 32), 256>>>(w_qkv, wqt, EMB, QKV_N);
    transpose_half<<<dim3(EMB / 32, EMB / 32), 256>>>(w_out, wot, EMB, EMB);

    // 1) qkv = x @ w_qkv -> fp16 Q,K + transposed fp16 V (smem-staged)
    hgemm<1><<<dim3(QKV_N / BN, SEQ / BM), 256, GEMM_SMEM>>>(
        ah, wqt, nullptr, qhp, khp, vtp, SEQ, QKV_N, EMB);
    // 2) attention -> fp16 ctx
    attn_h<<<dim3(SEQ / 64, NH), 128, ATTN_SMEM>>>(qhp, khp, vtp, chp);
    // 3) out = ctx @ w_out
    hgemm<0><<<dim3(EMB / BN, SEQ / BM), 256, GEMM_SMEM>>>(
        chp, wot, out, nullptr, nullptr, nullptr, SEQ, EMB, EMB);
}

// round 15
// speedup vs baseline: 1.0508x; 1.0508x over previous
#include <cuda_runtime.h>
#include <cuda_fp16.h>
#include <cstdint>

#define SEQ   4096
#define EMB   1024
#define NH    16
#define HD    64
#define WIN   256
#define QKV_N 3072

// ---- fp16 GEMM tiling (round-12 proven): 128x128x64, 8 warps, warp 64x32 ----
#define BM 128
#define BN 128
#define BK 64
#define STG 3
#define LHW 72
#define TILE_H (128 * LHW)
#define STAGE_H (2 * TILE_H)
#define GEMM_SMEM (STG * STAGE_H * 2)

// ---- attention (fp16): Q + double-buffered K/V; strides in halves ----
#define LH 72
#define QS_OFF  0
#define KS_OFF  (64 * LH)                 // + s * 64*LH
#define VS_OFF  (3 * 64 * LH)             // + s * 64*LH
#define ATTN_SMEM ((5 * 64 * LH) * 2)     // 46080 B

static __device__ __half g_ah[SEQ * EMB];      // x fp16 [seq][emb]
static __device__ __half g_wqt[QKV_N * EMB];   // w_qkv^T fp16 [N][K]
static __device__ __half g_wot[EMB * EMB];     // w_out^T fp16 [N][K]
static __device__ __half g_qh[SEQ * EMB];      // Q fp16
static __device__ __half g_kh[SEQ * EMB];      // K fp16
static __device__ __half g_vt[EMB * SEQ];      // V fp16 transposed [(h*64+d)][seq]
static __device__ __half g_ch[SEQ * EMB];      // ctx fp16

__device__ __forceinline__ uint32_t smem_u32(const void* p) {
    uint32_t a;
    asm("{ .reg .u64 t; cvta.to.shared.u64 t, %1; cvt.u32.u64 %0, t; }" : "=r"(a) : "l"(p));
    return a;
}
__device__ __forceinline__ void mma_f16(float d[4], const uint32_t a[4], const uint32_t b[2]) {
    asm volatile(
        "mma.sync.aligned.m16n8k16.row.col.f32.f16.f16.f32 "
        "{%0,%1,%2,%3}, {%4,%5,%6,%7}, {%8,%9}, {%0,%1,%2,%3};\n"
        : "+f"(d[0]), "+f"(d[1]), "+f"(d[2]), "+f"(d[3])
        : "r"(a[0]), "r"(a[1]), "r"(a[2]), "r"(a[3]), "r"(b[0]), "r"(b[1]));
}
__device__ __forceinline__ void ldsm4(uint32_t r[4], uint32_t addr) {
    asm volatile("ldmatrix.sync.aligned.m8n8.x4.shared.b16 {%0,%1,%2,%3}, [%4];"
                 : "=r"(r[0]), "=r"(r[1]), "=r"(r[2]), "=r"(r[3]) : "r"(addr));
}
__device__ __forceinline__ void cp16(const void* smem_dst, const void* gsrc) {
    uint32_t saddr = smem_u32(smem_dst);
    asm volatile("cp.async.cg.shared.global [%0], [%1], 16;\n" :: "r"(saddr), "l"(gsrc) : "memory");
}
__device__ __forceinline__ uint32_t h2u(__half2 v) { return *(uint32_t*)&v; }

// ---------------------------------------------------------------------------
__global__ __launch_bounds__(256) void to_half(const float4* __restrict__ src,
                                               __half2* __restrict__ dst, int n4) {
    int i = blockIdx.x * blockDim.x + threadIdx.x;
    if (i < n4) {
        float4 v = src[i];
        dst[2 * i]     = __floats2half2_rn(v.x, v.y);
        dst[2 * i + 1] = __floats2half2_rn(v.z, v.w);
    }
}

__global__ __launch_bounds__(256) void transpose_half(const float* __restrict__ W,
                                                      __half* __restrict__ T,
                                                      int K, int N) {
    __shared__ float tile[32][33];
    const int tx = threadIdx.x & 31, ty = threadIdx.x >> 5;
    const int n0 = blockIdx.x * 32, k0 = blockIdx.y * 32;
#pragma unroll
    for (int i = 0; i < 4; i++)
        tile[ty + 8 * i][tx] = W[(size_t)(k0 + ty + 8 * i) * N + n0 + tx];
    __syncthreads();
#pragma unroll
    for (int i = 0; i < 4; i++)
        T[(size_t)(n0 + ty + 8 * i) * K + k0 + tx] = __float2half_rn(tile[tx][ty + 8 * i]);
}

// ---------------------------------------------------------------------------
// fp16 tensor-core GEMM (round-12 proven). MODE 0: fp32 C. MODE 1: qkv split.
// ---------------------------------------------------------------------------
template <int MODE>
__global__ __launch_bounds__(256, 2) void hgemm(const __half* __restrict__ A,
                                                const __half* __restrict__ Bt,
                                                float* __restrict__ C,
                                                __half* __restrict__ qh,
                                                __half* __restrict__ kh,
                                                __half* __restrict__ vt,
                                                int M, int N, int K) {
    extern __shared__ __half smh[];
    const uint32_t sb = smem_u32(smh);

    const int t    = threadIdx.x;
    const int w    = t >> 5;
    const int lane = t & 31;
    const int wm   = w >> 2;
    const int wn   = w & 3;
    const int lr   = lane >> 2;
    const int lc   = lane & 3;
    const int bx   = blockIdx.x;
    const int by   = blockIdx.y;

    const int l15  = lane & 15;
    const int lhi8 = (lane >> 4) * 8;
    const int brow = ((lane >> 4) << 3) + (lane & 7);
    const int bk8  = ((lane >> 3) & 1) * 8;

    float acc[4][4][4];
#pragma unroll
    for (int i = 0; i < 4; i++)
#pragma unroll
        for (int j = 0; j < 4; j++)
#pragma unroll
            for (int c = 0; c < 4; c++) acc[i][j][c] = 0.0f;

    const int NT = K / BK;
    const int ldr = t >> 3;
    const int ldc = (t & 7) * 8;

#define LOAD_TILE(stage, ktile)                                                         \
    {                                                                                   \
        __half* Ad = smh + (stage) * STAGE_H;                                           \
        __half* Bd = Ad + TILE_H;                                                       \
        const int k0 = (ktile) * BK;                                                    \
        _Pragma("unroll")                                                               \
        for (int i = 0; i < 4; i++) {                                                   \
            int r = ldr + 32 * i;                                                       \
            cp16(&Ad[r * LHW + ldc], &A[(size_t)(by * BM + r) * K + k0 + ldc]);         \
            cp16(&Bd[r * LHW + ldc], &Bt[(size_t)(bx * BN + r) * K + k0 + ldc]);        \
        }                                                                               \
        asm volatile("cp.async.commit_group;\n" ::: "memory");                          \
    }

    LOAD_TILE(0, 0);
    LOAD_TILE(1, 1);

    for (int kt = 0; kt < NT; kt++) {
        if (kt + 2 < NT) asm volatile("cp.async.wait_group 1;\n" ::: "memory");
        else             asm volatile("cp.async.wait_group 0;\n" ::: "memory");
        __syncthreads();

        if (kt + 2 < NT) LOAD_TILE((kt + 2) % STG, kt + 2);

        const uint32_t Ab = sb + (uint32_t)((kt % STG) * STAGE_H) * 2;
        const uint32_t Bb = Ab + TILE_H * 2;

#pragma unroll
        for (int ks = 0; ks < 4; ks++) {
            uint32_t af[4][4], bq[2][4];
#pragma unroll
            for (int mi = 0; mi < 4; mi++)
                ldsm4(af[mi], Ab + (uint32_t)(((wm * 64 + mi * 16 + l15) * LHW) + ks * 16 + lhi8) * 2);
#pragma unroll
            for (int pr = 0; pr < 2; pr++)
                ldsm4(bq[pr], Bb + (uint32_t)(((wn * 32 + pr * 16 + brow) * LHW) + ks * 16 + bk8) * 2);
#pragma unroll
            for (int mi = 0; mi < 4; mi++)
#pragma unroll
                for (int ni = 0; ni < 4; ni++)
                    mma_f16(acc[mi][ni], af[mi], &bq[ni >> 1][(ni & 1) * 2]);
        }
    }

    if (MODE == 1 && bx >= (2 * EMB) / BN) {
        // ---- V tile: transpose through smem, coalesced V^T stores ----
        __syncthreads();
        __half* Vt = smh;                      // [128 dims][136 seq-halves]
#pragma unroll
        for (int mi = 0; mi < 4; mi++) {
            const int sl = wm * 64 + mi * 16 + lr;
#pragma unroll
            for (int ni = 0; ni < 4; ni++) {
                const int d0 = wn * 32 + ni * 8 + 2 * lc;
                Vt[d0 * 136 + sl]           = __float2half_rn(acc[mi][ni][0]);
                Vt[(d0 + 1) * 136 + sl]     = __float2half_rn(acc[mi][ni][1]);
                Vt[d0 * 136 + sl + 8]       = __float2half_rn(acc[mi][ni][2]);
                Vt[(d0 + 1) * 136 + sl + 8] = __float2half_rn(acc[mi][ni][3]);
            }
        }
        __syncthreads();
        const int vcol0 = bx * BN - 2 * EMB;
#pragma unroll
        for (int i = 0; i < 8; i++) {
            int id = t + 256 * i;
            int row = id >> 4, ch = id & 15;
            *(uint4*)&vt[(size_t)(vcol0 + row) * SEQ + by * BM + ch * 8] =
                *(const uint4*)&Vt[row * 136 + ch * 8];
        }
        return;
    }

#pragma unroll
    for (int mi = 0; mi < 4; mi++) {
        const int r0 = by * BM + wm * 64 + mi * 16 + lr;
#pragma unroll
        for (int ni = 0; ni < 4; ni++) {
            const int c0 = bx * BN + wn * 32 + ni * 8 + 2 * lc;
            float v0 = acc[mi][ni][0], v1 = acc[mi][ni][1];
            float v2 = acc[mi][ni][2], v3 = acc[mi][ni][3];
            if (MODE == 0) {
                *(float2*)&C[(size_t)r0 * N + c0]       = make_float2(v0, v1);
                *(float2*)&C[(size_t)(r0 + 8) * N + c0] = make_float2(v2, v3);
            } else {
                if (c0 < EMB) {
                    *(__half2*)&qh[(size_t)r0 * EMB + c0]       = __floats2half2_rn(v0, v1);
                    *(__half2*)&qh[(size_t)(r0 + 8) * EMB + c0] = __floats2half2_rn(v2, v3);
                } else {
                    const int cc = c0 - EMB;
                    *(__half2*)&kh[(size_t)r0 * EMB + cc]       = __floats2half2_rn(v0, v1);
                    *(__half2*)&kh[(size_t)(r0 + 8) * EMB + cc] = __floats2half2_rn(v2, v3);
                }
            }
        }
    }
#undef LOAD_TILE
}

// ---------------------------------------------------------------------------
// fp16 attention: Q fragments hoisted to registers; P packed directly into
// PV A-fragments (C-frag and A-frag register layouts coincide) — no P smem.
// ---------------------------------------------------------------------------
__global__ __launch_bounds__(128) void attn_h(const __half* __restrict__ qh,
                                              const __half* __restrict__ kh,
                                              const __half* __restrict__ vt,
                                              __half* __restrict__ ctx) {
    extern __shared__ __half sh[];
    __half* Qs = sh + QS_OFF;
    const uint32_t sb = smem_u32(sh);

    const int qb = blockIdx.x;
    const int h  = blockIdx.y;
    const int t  = threadIdx.x;
    const int w  = t >> 5;
    const int lane = t & 31;
    const int lr = lane >> 2;
    const int lc = lane & 3;
    const int q0 = qb * 64;
    const int col0 = h * HD;

    const int l15  = lane & 15;
    const int lhi8 = (lane >> 4) * 8;
    const int brow = ((lane >> 4) << 3) + (lane & 7);
    const int bk8  = ((lane >> 3) & 1) * 8;

#define LOADKV(s, kt)                                                                   \
    {                                                                                   \
        __half* Kd = sh + KS_OFF + (s) * 64 * LH;                                       \
        __half* Vd = sh + VS_OFF + (s) * 64 * LH;                                       \
        const int kk0 = (kt) * 64;                                                      \
        _Pragma("unroll")                                                               \
        for (int i = 0; i < 4; i++) {                                                   \
            int id = t + 128 * i;                                                       \
            int r = id >> 3, c = (id & 7) << 3;                                         \
            cp16(&Kd[r * LH + c], &kh[(size_t)(kk0 + r) * EMB + col0 + c]);             \
            cp16(&Vd[r * LH + c], &vt[(size_t)(col0 + r) * SEQ + kk0 + c]);             \
        }                                                                               \
        asm volatile("cp.async.commit_group;\n" ::: "memory");                          \
    }

    // Q loads share the first commit group
#pragma unroll
    for (int i = 0; i < 4; i++) {
        int id = t + 128 * i;
        int r = id >> 3, c = (id & 7) << 3;
        cp16(&Qs[r * LH + c], &qh[(size_t)(q0 + r) * EMB + col0 + c]);
    }
    const int ktlo = (qb >= 4) ? qb - 4 : 0;
    LOADKV(0, ktlo);

    asm volatile("cp.async.wait_group 0;\n" ::: "memory");
    __syncthreads();

    // hoist Q fragments (tile-invariant)
    const uint32_t qfb = sb + (uint32_t)(((16 * w + l15) * LH) + lhi8) * 2;
    uint32_t qf[4][4];
#pragma unroll
    for (int ks = 0; ks < 4; ks++) ldsm4(qf[ks], qfb + ks * 32);

    float o[8][4];
#pragma unroll
    for (int nt = 0; nt < 8; nt++)
#pragma unroll
        for (int c = 0; c < 4; c++) o[nt][c] = 0.0f;
    float m[2] = {-1e30f, -1e30f};
    float l[2] = {0.0f, 0.0f};

    for (int kt = ktlo; kt <= qb; kt++) {
        const int s = (kt - ktlo) & 1;
        const int k0 = kt * 64;
        const int mode = (kt == qb) ? 1 : ((qb >= 4 && kt == qb - 4) ? 2 : 0);

        if (kt != ktlo) {
            asm volatile("cp.async.wait_group 0;\n" ::: "memory");
            __syncthreads();
        }
        if (kt < qb) LOADKV(s ^ 1, kt + 1);

        const uint32_t Kb = sb + (uint32_t)((KS_OFF + s * 64 * LH) + (brow * LH) + bk8) * 2;
        const uint32_t Vb = sb + (uint32_t)((VS_OFF + s * 64 * LH) + (brow * LH) + bk8) * 2;

        // S = Q K^T
        float acc[8][4];
#pragma unroll
        for (int nt = 0; nt < 8; nt++)
#pragma unroll
            for (int c = 0; c < 4; c++) acc[nt][c] = 0.0f;

#pragma unroll
        for (int ks = 0; ks < 4; ks++) {
#pragma unroll
            for (int pr = 0; pr < 4; pr++) {
                uint32_t bq[4];
                ldsm4(bq, Kb + (uint32_t)(pr * 16 * LH) * 2 + ks * 32);
                mma_f16(acc[2 * pr], qf[ks], &bq[0]);
                mma_f16(acc[2 * pr + 1], qf[ks], &bq[2]);
            }
        }

        // masked online softmax; pack P directly into PV A-fragments
        uint32_t pa[4][4];
#pragma unroll
        for (int i = 0; i < 2; i++) {
            const int qi = q0 + 16 * w + lr + 8 * i;
            float sv[16];
            float mt = -1e30f;
#pragma unroll
            for (int nt = 0; nt < 8; nt++) {
#pragma unroll
                for (int c = 0; c < 2; c++) {
                    int kj = k0 + 8 * nt + 2 * lc + c;
                    bool ok = (mode == 0) ||
                              (mode == 1 ? (kj <= qi) : (kj > qi - WIN));
                    float sx = acc[nt][2 * i + c] * 0.125f;
                    sv[nt * 2 + c] = ok ? sx : -1e30f;
                    mt = fmaxf(mt, sv[nt * 2 + c]);
                }
            }
            mt = fmaxf(mt, __shfl_xor_sync(0xffffffffu, mt, 1));
            mt = fmaxf(mt, __shfl_xor_sync(0xffffffffu, mt, 2));

            float alpha = 1.0f;
            if (mt > m[i]) { alpha = __expf(m[i] - mt); m[i] = mt; }

            float ls = 0.0f;
            float p[16];
#pragma unroll
            for (int j = 0; j < 16; j++) {
                p[j] = (sv[j] > -1e29f) ? __expf(sv[j] - m[i]) : 0.0f;
                ls += p[j];
            }
            ls += __shfl_xor_sync(0xffffffffu, ls, 1);
            ls += __shfl_xor_sync(0xffffffffu, ls, 2);

            l[i] = l[i] * alpha + ls;
#pragma unroll
            for (int nt = 0; nt < 8; nt++) {
                o[nt][2 * i]     *= alpha;
                o[nt][2 * i + 1] *= alpha;
                // C-frag (rows lr / lr+8) == A-frag slot (nt&1)*2 + i of k-chunk nt>>1
                pa[nt >> 1][(nt & 1) * 2 + i] =
                    h2u(__floats2half2_rn(p[nt * 2], p[nt * 2 + 1]));
            }
        }

        // O += P V (pa straight from registers)
#pragma unroll
        for (int ks = 0; ks < 4; ks++) {
#pragma unroll
            for (int pr = 0; pr < 4; pr++) {
                uint32_t vq[4];
                ldsm4(vq, Vb + (uint32_t)(pr * 16 * LH) * 2 + ks * 32);
                mma_f16(o[2 * pr], pa[ks], &vq[0]);
                mma_f16(o[2 * pr + 1], pa[ks], &vq[2]);
            }
        }
    }

    // epilogue: normalize, fp16 ctx
    const float inv0 = 1.0f / l[0];
    const float inv1 = 1.0f / l[1];
    const int row0 = q0 + 16 * w + lr;
#pragma unroll
    for (int nt = 0; nt < 8; nt++) {
        int c0 = col0 + 8 * nt + 2 * lc;
        *(__half2*)&ctx[(size_t)row0 * EMB + c0] =
            __floats2half2_rn(o[nt][0] * inv0, o[nt][1] * inv0);
        *(__half2*)&ctx[(size_t)(row0 + 8) * EMB + c0] =
            __floats2half2_rn(o[nt][2] * inv1, o[nt][3] * inv1);
    }
#undef LOADKV
}

// ---------------------------------------------------------------------------
extern "C" void kernel_launch(void* const* d_in, const int* in_sizes, int n_in,
                              void* d_out, int out_size) {
    const float* x     = (const float*)d_in[0];
    const float* w_qkv = (const float*)d_in[2];
    const float* w_out = (const float*)d_in[3];
    float* out = (float*)d_out;

    __half *ah, *wqt, *wot, *qhp, *khp, *vtp, *chp;
    cudaGetSymbolAddress((void**)&ah, g_ah);
    cudaGetSymbolAddress((void**)&wqt, g_wqt);
    cudaGetSymbolAddress((void**)&wot, g_wot);
    cudaGetSymbolAddress((void**)&qhp, g_qh);
    cudaGetSymbolAddress((void**)&khp, g_kh);
    cudaGetSymbolAddress((void**)&vtp, g_vt);
    cudaGetSymbolAddress((void**)&chp, g_ch);

    cudaFuncSetAttribute(attn_h, cudaFuncAttributeMaxDynamicSharedMemorySize, ATTN_SMEM);
    cudaFuncSetAttribute(hgemm<0>, cudaFuncAttributeMaxDynamicSharedMemorySize, GEMM_SMEM);
    cudaFuncSetAttribute(hgemm<1>, cudaFuncAttributeMaxDynamicSharedMemorySize, GEMM_SMEM);

    // 0) prep
    to_half<<<(SEQ * EMB / 4 + 255) / 256, 256>>>((const float4*)x, (__half2*)ah, SEQ * EMB / 4);
    transpose_half<<<dim3(QKV_N / 32, EMB / 32), 256>>>(w_qkv, wqt, EMB, QKV_N);
    transpose_half<<<dim3(EMB / 32, EMB / 32), 256>>>(w_out, wot, EMB, EMB);

    // 1) qkv = x @ w_qkv -> fp16 Q,K + transposed fp16 V
    hgemm<1><<<dim3(QKV_N / BN, SEQ / BM), 256, GEMM_SMEM>>>(
        ah, wqt, nullptr, qhp, khp, vtp, SEQ, QKV_N, EMB);
    // 2) attention -> fp16 ctx
    attn_h<<<dim3(SEQ / 64, NH), 128, ATTN_SMEM>>>(qhp, khp, vtp, chp);
    // 3) out = ctx @ w_out
    hgemm<0><<<dim3(EMB / BN, SEQ / BM), 256, GEMM_SMEM>>>(
        chp, wot, out, nullptr, nullptr, nullptr, SEQ, EMB, EMB);
}